// round 10
// baseline (speedup 1.0000x reference)
#include <cuda_runtime.h>
#include <cuda_fp16.h>
#include <cstdint>

#define SLEN   1024
#define BSZ    32
#define HID    1024
#define INDIM  1024
#define M_TOTAL (SLEN * BSZ)   // 32768
#define NFUSED  (2 * HID)      // z|f stacked

// -------- scratch (__device__ globals) --------
__device__ float g_z [(size_t)M_TOTAL * HID];
__device__ float g_f [(size_t)M_TOTAL * HID];
// A fp16 fragments: [mt:2048][kt:64][lane:32] x uint4 {a0,a1,a2,a3}
__device__ uint4 g_ah[(size_t)2048 * 64 * 32];
// B fp16 fragments fused z|f: [nt:256][kp:32][lane:32] x uint4
__device__ uint4 g_bh[(size_t)256 * 32 * 32];

__device__ __forceinline__ uint32_t pkh(float a, float b) {
    __half2 h = __floats2half2_rn(a, b);
    return *(uint32_t*)&h;
}
__device__ __forceinline__ void cp16(uint32_t dst, const void* src) {
    asm volatile("cp.async.cg.shared.global [%0], [%1], 16;" :: "r"(dst), "l"(src));
}
__device__ __forceinline__ void cp4(uint32_t dst, const void* src) {
    asm volatile("cp.async.ca.shared.global [%0], [%1], 4;" :: "r"(dst), "l"(src));
}

// ============ prep A: x -> fp16 m16n8k16 A-fragments ============
__global__ __launch_bounds__(256)
void prep_a(const float* __restrict__ x, uint4* __restrict__ Af) {
    size_t u = (size_t)blockIdx.x * 256 + threadIdx.x;   // (mt,kt,lane)
    int lane = (int)(u & 31);
    int kt   = (int)((u >> 5) & 63);
    int mt   = (int)(u >> 11);
    int g = lane >> 2, tg = lane & 3;
    const float* r0 = x + (size_t)(mt * 16 + g) * INDIM + kt * 16;
    const float* r1 = r0 + 8 * INDIM;
    float2 p00 = *(const float2*)(r0 + 2 * tg);
    float2 p10 = *(const float2*)(r1 + 2 * tg);
    float2 p01 = *(const float2*)(r0 + 8 + 2 * tg);
    float2 p11 = *(const float2*)(r1 + 8 + 2 * tg);
    Af[u] = make_uint4(pkh(p00.x, p00.y), pkh(p10.x, p10.y),
                       pkh(p01.x, p01.y), pkh(p11.x, p11.y));
}

// ============ prep B: weights (fused z|f) -> fp16 B-fragments, kt-pairs ============
__global__ __launch_bounds__(256)
void prep_b(const float* __restrict__ wz, const float* __restrict__ wf,
            uint4* __restrict__ Bf) {
    size_t u = (size_t)blockIdx.x * 256 + threadIdx.x;   // (nt,kp,lane)
    int lane = (int)(u & 31);
    int kp   = (int)((u >> 5) & 31);
    int nt   = (int)(u >> 10);
    int g = lane >> 2, tg = lane & 3;
    int n = nt * 8 + g;
    const float* row = (n < HID) ? (wz + (size_t)n * INDIM)
                                 : (wf + (size_t)(n - HID) * INDIM);
    const float* c0 = row + kp * 32;
    float2 q00 = *(const float2*)(c0 + 2 * tg);
    float2 q01 = *(const float2*)(c0 + 8 + 2 * tg);
    float2 q10 = *(const float2*)(c0 + 16 + 2 * tg);
    float2 q11 = *(const float2*)(c0 + 24 + 2 * tg);
    Bf[u] = make_uint4(pkh(q00.x, q00.y), pkh(q01.x, q01.y),
                       pkh(q10.x, q10.y), pkh(q11.x, q11.y));
}

// ============ fp16 GEMM, 128x128 tile, 2 CTAs/SM, reversed m-order ============
#define BM 128
#define BN 128
#define NCH 16                    // 1024 / 64 (KC=64 = 4 k16-steps)
#define A_STAGE 16384
#define B_STAGE 16384
#define STAGE_BYTES (A_STAGE + B_STAGE)
#define SMEM_BYTES  (3 * STAGE_BYTES)    // 98304 -> 2 CTAs/SM

__device__ __forceinline__ void mma16(float* d, const uint32_t* a,
                                      uint32_t b0, uint32_t b1) {
    asm volatile(
        "mma.sync.aligned.m16n8k16.row.col.f32.f16.f16.f32 "
        "{%0,%1,%2,%3}, {%4,%5,%6,%7}, {%8,%9}, {%0,%1,%2,%3};"
        : "+f"(d[0]), "+f"(d[1]), "+f"(d[2]), "+f"(d[3])
        : "r"(a[0]), "r"(a[1]), "r"(a[2]), "r"(a[3]), "r"(b0), "r"(b1));
}

__global__ __launch_bounds__(256, 2)
void gemm_tc(const uint4* __restrict__ Af, const uint4* __restrict__ Bf,
             const float* __restrict__ bz, const float* __restrict__ bfb) {
    extern __shared__ char smemc[];
    const int tid  = threadIdx.x;
    const int lane = tid & 31;
    const int wid  = tid >> 5;
    const int wm   = wid >> 2;
    const int wn   = wid & 3;
    // reversed m-order: low-s tiles written LAST -> hot in L2 when scan starts
    const int yb   = (int)(gridDim.y - 1 - blockIdx.y);
    const int mt0  = yb * (BM / 16);
    const int nt0  = blockIdx.x * (BN / 8);

    float d[4][4][4];
#pragma unroll
    for (int i = 0; i < 4; i++)
#pragma unroll
        for (int j = 0; j < 4; j++)
#pragma unroll
            for (int q = 0; q < 4; q++) d[i][j][q] = 0.f;

    auto load_chunk = [&](int st, int c) {
        char* stA = smemc + st * STAGE_BYTES;
        char* stB = stA + A_STAGE;
        const int ktg0 = c * 4;
        const int kpg0 = c * 2;
#pragma unroll
        for (int t = 0; t < 4; t++) {          // A: 1024 x 16B
            int idx = tid + t * 256;
            int l = idx & 31, kt = (idx >> 5) & 3, mtl = idx >> 7;
            const uint4* src = Af +
                (((size_t)(mt0 + mtl) * 64) + (ktg0 + kt)) * 32 + l;
            cp16((uint32_t)__cvta_generic_to_shared(stA + idx * 16), src);
        }
#pragma unroll
        for (int t = 0; t < 4; t++) {          // B: 1024 x 16B
            int idx = tid + t * 256;
            int l = idx & 31, kp = (idx >> 5) & 1, ntl = idx >> 6;
            const uint4* src = Bf +
                (((size_t)(nt0 + ntl) * 32) + (kpg0 + kp)) * 32 + l;
            cp16((uint32_t)__cvta_generic_to_shared(stB + idx * 16), src);
        }
        asm volatile("cp.async.commit_group;" ::: "memory");
    };

    load_chunk(0, 0);
    load_chunk(1, 1);

    for (int c = 0; c < NCH; ++c) {
        if (c + 1 < NCH) asm volatile("cp.async.wait_group 1;" ::: "memory");
        else             asm volatile("cp.async.wait_group 0;" ::: "memory");
        __syncthreads();
        if (c + 2 < NCH) load_chunk((c + 2) % 3, c + 2);

        const int st = c % 3;
        const char* stA = smemc + st * STAGE_BYTES;
        const char* stB = stA + A_STAGE;
#pragma unroll
        for (int kp = 0; kp < 2; kp++) {
            uint32_t a0[4][4], a1[4][4];
#pragma unroll
            for (int i = 0; i < 4; i++) {
                int mtl = wm * 4 + i;
                uint4 v0 = *(const uint4*)(stA + ((mtl * 4 + 2 * kp)     * 32 + lane) * 16);
                uint4 v1 = *(const uint4*)(stA + ((mtl * 4 + 2 * kp + 1) * 32 + lane) * 16);
                a0[i][0]=v0.x; a0[i][1]=v0.y; a0[i][2]=v0.z; a0[i][3]=v0.w;
                a1[i][0]=v1.x; a1[i][1]=v1.y; a1[i][2]=v1.z; a1[i][3]=v1.w;
            }
#pragma unroll
            for (int j = 0; j < 4; j++) {
                int ntl = wn * 4 + j;
                uint4 b4 = *(const uint4*)(stB + ((ntl * 2 + kp) * 32 + lane) * 16);
#pragma unroll
                for (int i = 0; i < 4; i++) {
                    mma16(d[i][j], a0[i], b4.x, b4.y);
                    mma16(d[i][j], a1[i], b4.z, b4.w);
                }
            }
        }
    }

    // ---- epilogue: +bias, 0.5x for f-half ----
    const int g  = lane >> 2, tg = lane & 3;
    const int n0f = nt0 * 8;
    const bool isF = (n0f >= HID);
    float*       outp  = isF ? g_f : g_z;
    const float* bp    = isF ? bfb : bz;
    const float  scale = isF ? 0.5f : 1.0f;
    const int colBase  = (n0f - (isF ? HID : 0)) + wn * 32;

#pragma unroll
    for (int j = 0; j < 4; j++) {
        const int col = colBase + j * 8 + 2 * tg;
        const float2 bbv = *(const float2*)(bp + col);
#pragma unroll
        for (int i = 0; i < 4; i++) {
            const size_t row = (size_t)yb * BM + wm * 64 + i * 16 + g;
            float2 v0, v1;
            v0.x = scale * (d[i][j][0] + bbv.x);
            v0.y = scale * (d[i][j][1] + bbv.y);
            v1.x = scale * (d[i][j][2] + bbv.x);
            v1.y = scale * (d[i][j][3] + bbv.y);
            *(float2*)(outp + row * HID + col)       = v0;
            *(float2*)(outp + (row + 8) * HID + col) = v1;
        }
    }
}

// ============ scan: cp.async ring, 1 ch/thread, 32 thr/block, 1024 blocks ============
#define PF 32

__device__ __forceinline__ float tanh_fast(float v) {
    float r;
    asm("tanh.approx.f32 %0, %1;" : "=f"(r) : "f"(v));
    return r;
}

__global__ __launch_bounds__(32)
void scan_kernel(const float* __restrict__ state,
                 const float* __restrict__ wvz, const float* __restrict__ wvf,
                 float* __restrict__ out) {
    __shared__ float buf[PF][32][2];   // 8KB/block
    const int t = threadIdx.x;
    const int C = blockIdx.x * 32 + t;
    const int h0 = C & (HID - 1);

    float cell = state[C];
    const float wz  = wvz[h0];
    const float wfh = 0.5f * wvf[h0];

    const float* zsrc = g_z + C;
    const float* fsrc = g_f + C;

#pragma unroll 4
    for (int s = 0; s < PF; s++) {
        cp4((uint32_t)__cvta_generic_to_shared(&buf[s][t][0]), zsrc + (size_t)s * M_TOTAL);
        cp4((uint32_t)__cvta_generic_to_shared(&buf[s][t][1]), fsrc + (size_t)s * M_TOTAL);
        asm volatile("cp.async.commit_group;" ::: "memory");
    }

#pragma unroll 1
    for (int s = 0; s < SLEN; s++) {
        asm volatile("cp.async.wait_group %0;" :: "n"(PF - 1) : "memory");
        const int slot = s & (PF - 1);
        float zv = buf[slot][t][0];
        float fv = buf[slot][t][1];
        if (s + PF < SLEN) {
            cp4((uint32_t)__cvta_generic_to_shared(&buf[slot][t][0]),
                zsrc + (size_t)(s + PF) * M_TOTAL);
            cp4((uint32_t)__cvta_generic_to_shared(&buf[slot][t][1]),
                fsrc + (size_t)(s + PF) * M_TOTAL);
        }
        asm volatile("cp.async.commit_group;" ::: "memory");

        float zpart = tanh_fast(fmaf(wz,  cell, zv));
        float tt    = tanh_fast(fmaf(wfh, cell, fv));
        float fpart = fmaf(0.5f, tt, 0.5f);
        cell = fmaf(fpart, cell - zpart, zpart);
        out[(size_t)s * M_TOTAL + C] = cell;
    }
}

// ============ launch ============
extern "C" void kernel_launch(void* const* d_in, const int* in_sizes, int n_in,
                              void* d_out, int out_size) {
    const float* x      = (const float*)d_in[0];
    const float* state  = (const float*)d_in[1];
    const float* wm_z   = (const float*)d_in[2];
    const float* wm_f   = (const float*)d_in[3];
    const float* wv_z   = (const float*)d_in[4];
    const float* wv_f   = (const float*)d_in[5];
    const float* bias_z = (const float*)d_in[6];
    const float* bias_f = (const float*)d_in[7];
    float* out = (float*)d_out;

    uint4 *af, *bf;
    cudaGetSymbolAddress((void**)&af, g_ah);
    cudaGetSymbolAddress((void**)&bf, g_bh);

    cudaFuncSetAttribute(gemm_tc, cudaFuncAttributeMaxDynamicSharedMemorySize, SMEM_BYTES);

    prep_a<<<16384, 256>>>(x, af);
    prep_b<<<1024, 256>>>(wm_z, wm_f, bf);

    dim3 grid(NFUSED / BN, M_TOTAL / BM);   // (16, 256)
    gemm_tc<<<grid, 256, SMEM_BYTES>>>(af, bf, bias_z, bias_f);

    scan_kernel<<<1024, 32>>>(state, wv_z, wv_f, out);
}

// round 11
// speedup vs baseline: 1.0950x; 1.0950x over previous
#include <cuda_runtime.h>
#include <cuda_fp16.h>
#include <cstdint>

#define SLEN   1024
#define BSZ    32
#define HID    1024
#define INDIM  1024
#define M_TOTAL (SLEN * BSZ)   // 32768
#define NFUSED  (2 * HID)

// -------- scratch (__device__ globals) --------
// interleaved pre-activations: word (m, h) = half2{ z+bz , 0.5*(f+bf) }
__device__ uint32_t g_zf[(size_t)M_TOTAL * HID];          // 128 MB
// A fp16 fragments: [mt:2048][kt:64][lane:32] x uint4
__device__ uint4 g_ah[(size_t)2048 * 64 * 32];
// B fp16 fragments fused z|f: [nt:256][kp:32][lane:32] x uint4
__device__ uint4 g_bh[(size_t)256 * 32 * 32];

__device__ __forceinline__ uint32_t pkh(float a, float b) {
    __half2 h = __floats2half2_rn(a, b);
    return *(uint32_t*)&h;
}
__device__ __forceinline__ void cp16(uint32_t dst, const void* src) {
    asm volatile("cp.async.cg.shared.global [%0], [%1], 16;" :: "r"(dst), "l"(src));
}
__device__ __forceinline__ void cp4(uint32_t dst, const void* src) {
    asm volatile("cp.async.ca.shared.global [%0], [%1], 4;" :: "r"(dst), "l"(src));
}

// ============ prep A: x -> fp16 m16n8k16 A-fragments ============
__global__ __launch_bounds__(256)
void prep_a(const float* __restrict__ x, uint4* __restrict__ Af) {
    size_t u = (size_t)blockIdx.x * 256 + threadIdx.x;
    int lane = (int)(u & 31);
    int kt   = (int)((u >> 5) & 63);
    int mt   = (int)(u >> 11);
    int g = lane >> 2, tg = lane & 3;
    const float* r0 = x + (size_t)(mt * 16 + g) * INDIM + kt * 16;
    const float* r1 = r0 + 8 * INDIM;
    float2 p00 = *(const float2*)(r0 + 2 * tg);
    float2 p10 = *(const float2*)(r1 + 2 * tg);
    float2 p01 = *(const float2*)(r0 + 8 + 2 * tg);
    float2 p11 = *(const float2*)(r1 + 8 + 2 * tg);
    Af[u] = make_uint4(pkh(p00.x, p00.y), pkh(p10.x, p10.y),
                       pkh(p01.x, p01.y), pkh(p11.x, p11.y));
}

// ============ prep B: weights (fused z|f) -> fp16 B-fragments, kt-pairs ============
__global__ __launch_bounds__(256)
void prep_b(const float* __restrict__ wz, const float* __restrict__ wf,
            uint4* __restrict__ Bf) {
    size_t u = (size_t)blockIdx.x * 256 + threadIdx.x;
    int lane = (int)(u & 31);
    int kp   = (int)((u >> 5) & 31);
    int nt   = (int)(u >> 10);
    int g = lane >> 2, tg = lane & 3;
    int n = nt * 8 + g;
    const float* row = (n < HID) ? (wz + (size_t)n * INDIM)
                                 : (wf + (size_t)(n - HID) * INDIM);
    const float* c0 = row + kp * 32;
    float2 q00 = *(const float2*)(c0 + 2 * tg);
    float2 q01 = *(const float2*)(c0 + 8 + 2 * tg);
    float2 q10 = *(const float2*)(c0 + 16 + 2 * tg);
    float2 q11 = *(const float2*)(c0 + 24 + 2 * tg);
    Bf[u] = make_uint4(pkh(q00.x, q00.y), pkh(q01.x, q01.y),
                       pkh(q10.x, q10.y), pkh(q11.x, q11.y));
}

// ============ fp16 GEMM: each CTA computes matching z AND f cols ============
// CTA 256 thr (8 warps 2x4), tile 128(M) x [64 z-cols + 64 f-cols], KC=64, 3-stage
#define BM 128
#define NCH 16
#define A_STAGE 16384
#define B_STAGE 16384             // 16 n8-tiles (8 z + 8 f) * 2kp * 32lane * 16B
#define STAGE_BYTES (A_STAGE + B_STAGE)
#define SMEM_BYTES  (3 * STAGE_BYTES)    // 98304 -> 2 CTAs/SM

__device__ __forceinline__ void mma16(float* d, const uint32_t* a,
                                      uint32_t b0, uint32_t b1) {
    asm volatile(
        "mma.sync.aligned.m16n8k16.row.col.f32.f16.f16.f32 "
        "{%0,%1,%2,%3}, {%4,%5,%6,%7}, {%8,%9}, {%0,%1,%2,%3};"
        : "+f"(d[0]), "+f"(d[1]), "+f"(d[2]), "+f"(d[3])
        : "r"(a[0]), "r"(a[1]), "r"(a[2]), "r"(a[3]), "r"(b0), "r"(b1));
}

__global__ __launch_bounds__(256, 2)
void gemm_tc(const uint4* __restrict__ Af, const uint4* __restrict__ Bf,
             const float* __restrict__ bz, const float* __restrict__ bfb) {
    extern __shared__ char smemc[];
    const int tid  = threadIdx.x;
    const int lane = tid & 31;
    const int wid  = tid >> 5;
    const int wm   = wid >> 2;                 // 0..1 : 64 M-rows
    const int wn   = wid & 3;                  // 0..3 : 16 cols (z) + 16 (f)
    const int mt0  = blockIdx.y * (BM / 16);
    const int nt0z = blockIdx.x * 8;           // z n8-tile base (cols = nt0z*8)

    float d[4][4][4];                          // j: 0,1 = z tiles; 2,3 = f tiles
#pragma unroll
    for (int i = 0; i < 4; i++)
#pragma unroll
        for (int j = 0; j < 4; j++)
#pragma unroll
            for (int q = 0; q < 4; q++) d[i][j][q] = 0.f;

    auto load_chunk = [&](int st, int c) {
        char* stA = smemc + st * STAGE_BYTES;
        char* stB = stA + A_STAGE;
        const int ktg0 = c * 4;
        const int kpg0 = c * 2;
#pragma unroll
        for (int t = 0; t < 4; t++) {          // A: 1024 x 16B
            int idx = tid + t * 256;
            int l = idx & 31, kt = (idx >> 5) & 3, mtl = idx >> 7;
            const uint4* src = Af +
                (((size_t)(mt0 + mtl) * 64) + (ktg0 + kt)) * 32 + l;
            cp16((uint32_t)__cvta_generic_to_shared(stA + idx * 16), src);
        }
#pragma unroll
        for (int t = 0; t < 4; t++) {          // B: 1024 x 16B (8 z-tiles + 8 f-tiles)
            int idx = tid + t * 256;
            int l = idx & 31, kp = (idx >> 5) & 1, ntl = idx >> 6;  // 0..15
            int ntg = (ntl < 8) ? (nt0z + ntl) : (128 + nt0z + (ntl - 8));
            const uint4* src = Bf +
                (((size_t)ntg * 32) + (kpg0 + kp)) * 32 + l;
            cp16((uint32_t)__cvta_generic_to_shared(stB + idx * 16), src);
        }
        asm volatile("cp.async.commit_group;" ::: "memory");
    };

    load_chunk(0, 0);
    load_chunk(1, 1);

    for (int c = 0; c < NCH; ++c) {
        if (c + 1 < NCH) asm volatile("cp.async.wait_group 1;" ::: "memory");
        else             asm volatile("cp.async.wait_group 0;" ::: "memory");
        __syncthreads();
        if (c + 2 < NCH) load_chunk((c + 2) % 3, c + 2);

        const int st = c % 3;
        const char* stA = smemc + st * STAGE_BYTES;
        const char* stB = stA + A_STAGE;
#pragma unroll
        for (int kp = 0; kp < 2; kp++) {
            uint32_t a0[4][4], a1[4][4];
#pragma unroll
            for (int i = 0; i < 4; i++) {
                int mtl = wm * 4 + i;
                uint4 v0 = *(const uint4*)(stA + ((mtl * 4 + 2 * kp)     * 32 + lane) * 16);
                uint4 v1 = *(const uint4*)(stA + ((mtl * 4 + 2 * kp + 1) * 32 + lane) * 16);
                a0[i][0]=v0.x; a0[i][1]=v0.y; a0[i][2]=v0.z; a0[i][3]=v0.w;
                a1[i][0]=v1.x; a1[i][1]=v1.y; a1[i][2]=v1.z; a1[i][3]=v1.w;
            }
#pragma unroll
            for (int j = 0; j < 4; j++) {
                // j=0,1 -> z tiles (smem ntl = wn*2+j); j=2,3 -> f tiles (8 + wn*2 + j-2)
                int ntl = (j < 2) ? (wn * 2 + j) : (8 + wn * 2 + (j - 2));
                uint4 b4 = *(const uint4*)(stB + ((ntl * 2 + kp) * 32 + lane) * 16);
#pragma unroll
                for (int i = 0; i < 4; i++) {
                    mma16(d[i][j], a0[i], b4.x, b4.y);
                    mma16(d[i][j], a1[i], b4.z, b4.w);
                }
            }
        }
    }

    // ---- epilogue: pack half2{z+bz, 0.5(f+bf)}, 8B coalesced stores ----
    const int g  = lane >> 2, tg = lane & 3;
    const int c0 = blockIdx.x * 64 + wn * 16;  // column base (same for z and f)

#pragma unroll
    for (int jz = 0; jz < 2; jz++) {
        const int col = c0 + jz * 8 + 2 * tg;
        const float2 bbz = *(const float2*)(bz  + col);
        const float2 bbf = *(const float2*)(bfb + col);
#pragma unroll
        for (int i = 0; i < 4; i++) {
            const size_t row = (size_t)blockIdx.y * BM + wm * 64 + i * 16 + g;
            uint2 w0, w1;
            w0.x = pkh(d[i][jz][0] + bbz.x, 0.5f * (d[i][jz + 2][0] + bbf.x));
            w0.y = pkh(d[i][jz][1] + bbz.y, 0.5f * (d[i][jz + 2][1] + bbf.y));
            w1.x = pkh(d[i][jz][2] + bbz.x, 0.5f * (d[i][jz + 2][2] + bbf.x));
            w1.y = pkh(d[i][jz][3] + bbz.y, 0.5f * (d[i][jz + 2][3] + bbf.y));
            *(uint2*)(g_zf + row * HID + col)       = w0;
            *(uint2*)(g_zf + (row + 8) * HID + col) = w1;
        }
    }
}

// ============ scan: one half2 cp.async per step, 1024 x 32 ============
#define PF 32

__device__ __forceinline__ float tanh_fast(float v) {
    float r;
    asm("tanh.approx.f32 %0, %1;" : "=f"(r) : "f"(v));
    return r;
}

__global__ __launch_bounds__(32)
void scan_kernel(const float* __restrict__ state,
                 const float* __restrict__ wvz, const float* __restrict__ wvf,
                 float* __restrict__ out) {
    __shared__ uint32_t buf[PF][32];   // 4KB
    const int t = threadIdx.x;
    const int C = blockIdx.x * 32 + t;
    const int h0 = C & (HID - 1);

    float cell = state[C];
    const float wz  = wvz[h0];
    const float wfh = 0.5f * wvf[h0];

    const uint32_t* src = g_zf + C;

#pragma unroll 4
    for (int s = 0; s < PF; s++) {
        cp4((uint32_t)__cvta_generic_to_shared(&buf[s][t]), src + (size_t)s * M_TOTAL);
        asm volatile("cp.async.commit_group;" ::: "memory");
    }

#pragma unroll 1
    for (int s = 0; s < SLEN; s++) {
        asm volatile("cp.async.wait_group %0;" :: "n"(PF - 1) : "memory");
        const int slot = s & (PF - 1);
        uint32_t v = buf[slot][t];
        if (s + PF < SLEN) {
            cp4((uint32_t)__cvta_generic_to_shared(&buf[slot][t]),
                src + (size_t)(s + PF) * M_TOTAL);
        }
        asm volatile("cp.async.commit_group;" ::: "memory");

        float2 zf = __half22float2(*(__half2*)&v);
        float zpart = tanh_fast(fmaf(wz,  cell, zf.x));
        float tt    = tanh_fast(fmaf(wfh, cell, zf.y));
        float fpart = fmaf(0.5f, tt, 0.5f);
        cell = fmaf(fpart, cell - zpart, zpart);
        out[(size_t)s * M_TOTAL + C] = cell;
    }
}

// ============ launch ============
extern "C" void kernel_launch(void* const* d_in, const int* in_sizes, int n_in,
                              void* d_out, int out_size) {
    const float* x      = (const float*)d_in[0];
    const float* state  = (const float*)d_in[1];
    const float* wm_z   = (const float*)d_in[2];
    const float* wm_f   = (const float*)d_in[3];
    const float* wv_z   = (const float*)d_in[4];
    const float* wv_f   = (const float*)d_in[5];
    const float* bias_z = (const float*)d_in[6];
    const float* bias_f = (const float*)d_in[7];
    float* out = (float*)d_out;

    uint4 *af, *bf;
    cudaGetSymbolAddress((void**)&af, g_ah);
    cudaGetSymbolAddress((void**)&bf, g_bh);

    cudaFuncSetAttribute(gemm_tc, cudaFuncAttributeMaxDynamicSharedMemorySize, SMEM_BYTES);

    prep_a<<<16384, 256>>>(x, af);
    prep_b<<<1024, 256>>>(wm_z, wm_f, bf);

    dim3 grid(16, M_TOTAL / BM);   // 16 col-groups x 256 m-tiles
    gemm_tc<<<grid, 256, SMEM_BYTES>>>(af, bf, bias_z, bias_f);

    scan_kernel<<<1024, 32>>>(state, wv_z, wv_f, out);
}